// round 10
// baseline (speedup 1.0000x reference)
#include <cuda_runtime.h>
#include <cuda_fp16.h>
#include <cstdint>

#define NROWS 8192
#define D_IN  64
#define D_OUT 32000
#define MT 128
#define NT 128
#define NBLK   (D_OUT / NT)     // 250
#define NBLK2  (NBLK * 2)       // 500 partials per row
#define NSTRIP (NROWS / MT)     // 64 row strips
#define NGROUP (NSTRIP + 1)     // 65 ticket groups
#define NTICK  (NGROUP * 500)   // 32500 tickets

// smem rows: 32 words fp16 + 4 pad = 36 words (144B) -> all ldmatrix phases
// bank-conflict-free.
#define PITCH 36
#define LOG2E 1.4426950408889634f

// -------------------- device scratch --------------------
__device__ uint32_t g_wprep[D_OUT * 32];   // [n][32] f16x2 of W^T * log2e
__device__ uint32_t g_xprep[NROWS * 32];   // [row][32] f16x2 of 1/x
__device__ float    g_partials[NROWS * NBLK2];
__device__ float    g_rowinv[NROWS];
__device__ uint32_t g_ticket;
__device__ uint32_t g_done1[NSTRIP];
__device__ uint32_t g_flag2[NSTRIP];

__device__ __forceinline__ uint32_t pack_h2(float a, float b) {
    uint32_t lo = __half_as_ushort(__float2half_rn(a));
    uint32_t hi = __half_as_ushort(__float2half_rn(b));
    return lo | (hi << 16);
}
__device__ __forceinline__ uint32_t smem_u32(const void* p) {
    uint32_t a;
    asm("{ .reg .u64 t; cvta.to.shared.u64 t, %1; cvt.u32.u64 %0, t; }" : "=r"(a) : "l"(p));
    return a;
}
__device__ __forceinline__ void cpa16(uint32_t s, const void* g) {
    asm volatile("cp.async.cg.shared.global [%0], [%1], 16;" :: "r"(s), "l"(g));
}
__device__ __forceinline__ void ldsm4(uint32_t* r, uint32_t a) {
    asm volatile("ldmatrix.sync.aligned.m8n8.x4.shared.b16 {%0,%1,%2,%3}, [%4];"
                 : "=r"(r[0]), "=r"(r[1]), "=r"(r[2]), "=r"(r[3]) : "r"(a));
}
__device__ __forceinline__ void mma_f16(float* c, const uint32_t* a, uint32_t b0, uint32_t b1) {
    asm volatile(
        "mma.sync.aligned.m16n8k16.row.col.f32.f16.f16.f32 "
        "{%0,%1,%2,%3}, {%4,%5,%6,%7}, {%8,%9}, {%0,%1,%2,%3};"
        : "+f"(c[0]), "+f"(c[1]), "+f"(c[2]), "+f"(c[3])
        : "r"(a[0]), "r"(a[1]), "r"(a[2]), "r"(a[3]), "r"(b0), "r"(b1));
}
__device__ __forceinline__ float ex2(float x) {
    float y;
    asm("ex2.approx.f32 %0, %1;" : "=f"(y) : "f"(x));
    return y;
}

// ---------------------------------------------------------------------------
__global__ void init_kernel() {
    int i = threadIdx.x;
    if (i == 0) g_ticket = 0;
    if (i < NSTRIP) { g_done1[i] = 0; g_flag2[i] = 0; }
}

// ---------------------------------------------------------------------------
// prep_w: W[64][32000] * log2e -> fp16 rows [n][32 words]
// ---------------------------------------------------------------------------
__global__ __launch_bounds__(256) void prep_w_kernel(const float* __restrict__ w) {
    int n = blockIdx.x * 256 + threadIdx.x;
    uint32_t hi[32];
#pragma unroll
    for (int j = 0; j < 32; ++j) {
        float v0 = w[(2 * j) * D_OUT + n] * LOG2E;
        float v1 = w[(2 * j + 1) * D_OUT + n] * LOG2E;
        hi[j] = pack_h2(v0, v1);
    }
    uint4* d = reinterpret_cast<uint4*>(g_wprep) + (size_t)n * 8;
#pragma unroll
    for (int j = 0; j < 8; ++j)
        d[j] = make_uint4(hi[4*j], hi[4*j+1], hi[4*j+2], hi[4*j+3]);
}

// ---------------------------------------------------------------------------
// prep_x: x[8192][64] -> fp16 rows [r][32 words] of 1/x. 2 threads per row.
// ---------------------------------------------------------------------------
__global__ __launch_bounds__(256) void prep_x_kernel(const float* __restrict__ x) {
    int tid = blockIdx.x * 256 + threadIdx.x;
    int row = tid >> 1, half = tid & 1;
    const float4* xr = reinterpret_cast<const float4*>(&x[(size_t)row * D_IN + half * 32]);
    uint32_t hi[16];
#pragma unroll
    for (int j = 0; j < 8; ++j) {
        float4 v = xr[j];
        hi[2*j]   = pack_h2(1.0f / v.x, 1.0f / v.y);
        hi[2*j+1] = pack_h2(1.0f / v.z, 1.0f / v.w);
    }
    uint4* d = reinterpret_cast<uint4*>(g_xprep) + (size_t)row * 8 + half * 4;
#pragma unroll
    for (int j = 0; j < 4; ++j)
        d[j] = make_uint4(hi[4*j], hi[4*j+1], hi[4*j+2], hi[4*j+3]);
}

// ---------------------------------------------------------------------------
// Persistent fused kernel: work-queue over 65 groups of 500 tickets.
// Group g: tickets [0,250) = pass1 tiles of strip g (if g<64),
//          tickets [250,500) = pass2 tiles of strip g-1 (if g>=1).
// ---------------------------------------------------------------------------
__global__ __launch_bounds__(256, 2)
void fused_kernel(float* __restrict__ out) {
    extern __shared__ uint32_t smem[];
    uint32_t* sA = smem;                 // [128][36]
    uint32_t* sB = smem + 128 * PITCH;   // [128][36]
    __shared__ uint32_t sh_ticket;
    __shared__ uint32_t sh_last;

    const int tid  = threadIdx.x;
    const int wid  = tid >> 5;
    const int lane = tid & 31;
    const uint32_t sA_a = smem_u32(sA);
    const uint32_t sB_a = smem_u32(sB);

    // fragment lane constants
    const int wm = wid & 3;
    const int wn = wid >> 2;
    const int g  = lane >> 2;
    const int t  = lane & 3;
    const int arow = lane & 15;
    const int ako  = (lane >> 4) * 16;
    const int brow = (lane & 7) + ((lane >> 4) & 1) * 8;
    const int bko  = ((lane >> 3) & 1) * 16;

    for (;;) {
        __syncthreads();     // protect smem from previous tile's readers
        if (tid == 0) sh_ticket = atomicAdd(&g_ticket, 1u);
        __syncthreads();
        const uint32_t tk = sh_ticket;
        if (tk >= NTICK) break;

        const int grp = tk / 500;
        const int r   = tk % 500;
        const int is_p2 = (r >= 250);
        const int strip = is_p2 ? (grp - 1) : grp;
        const int blk   = is_p2 ? (r - 250) : r;
        if ((!is_p2 && grp >= NSTRIP) || (is_p2 && grp < 1)) continue;  // no-op ticket

        const int m0 = strip * MT;
        const int n0 = blk * NT;

        // ---- prologue: cp.async both tiles (1024 uint4 each, 4/thread) ----
        {
            const uint4* gA = reinterpret_cast<const uint4*>(g_xprep + (size_t)m0 * 32);
            const uint4* gB = reinterpret_cast<const uint4*>(g_wprep + (size_t)n0 * 32);
#pragma unroll
            for (int j = 0; j < 4; ++j) {
                int f = tid + 256 * j;
                uint32_t doff = ((f >> 3) * PITCH + (f & 7) * 4) * 4;
                cpa16(sA_a + doff, gA + f);
                cpa16(sB_a + doff, gB + f);
            }
            asm volatile("cp.async.commit_group;" ::: "memory");
        }

        // ---- pass2: wait for this strip's rowinv (hidden behind cp.async) ----
        if (is_p2) {
            if (tid == 0) {
                while (*(volatile uint32_t*)&g_flag2[strip] == 0u) __nanosleep(128);
                __threadfence();
            }
        }

        asm volatile("cp.async.wait_group 0;" ::: "memory");
        __syncthreads();

        // ---- fragment addresses ----
        uint32_t aBase[2];
#pragma unroll
        for (int mi = 0; mi < 2; ++mi)
            aBase[mi] = sA_a + (uint32_t)(wm * 32 + mi * 16 + arow) * (PITCH * 4u) + ako;
        uint32_t bBase[4];
#pragma unroll
        for (int np = 0; np < 4; ++np)
            bBase[np] = sB_a + (uint32_t)((wn * 64 + np * 16 + brow) * (PITCH * 4u)) + bko;

        float acc[2][8][4];
#pragma unroll
        for (int mi = 0; mi < 2; ++mi)
#pragma unroll
            for (int ni = 0; ni < 8; ++ni)
#pragma unroll
                for (int c = 0; c < 4; ++c) acc[mi][ni][c] = 0.0f;

        // ---- mainloop ----
#pragma unroll
        for (int kc = 0; kc < 4; ++kc) {
            const uint32_t ko = kc * 32u;
            uint32_t ah[2][4];
#pragma unroll
            for (int mi = 0; mi < 2; ++mi)
                ldsm4(ah[mi], aBase[mi] + ko);
#pragma unroll
            for (int np = 0; np < 4; ++np) {
                uint32_t b[4];
                ldsm4(b, bBase[np] + ko);
#pragma unroll
                for (int mi = 0; mi < 2; ++mi) {
                    mma_f16(acc[mi][2*np],     ah[mi], b[0], b[1]);
                    mma_f16(acc[mi][2*np + 1], ah[mi], b[2], b[3]);
                }
            }
        }

        // ---- epilogue ----
        if (is_p2) {
#pragma unroll
            for (int mi = 0; mi < 2; ++mi) {
                const int rg = m0 + wm * 32 + mi * 16 + g;
                const float inv0 = __ldcg(&g_rowinv[rg]);
                const float inv8 = __ldcg(&g_rowinv[rg + 8]);
                float* r0p = out + (size_t)rg * D_OUT + n0 + wn * 64 + t * 2;
                float* r8p = r0p + (size_t)8 * D_OUT;
#pragma unroll
                for (int ni = 0; ni < 8; ++ni) {
                    float e0 = ex2(acc[mi][ni][0]);
                    float e1 = ex2(acc[mi][ni][1]);
                    float e2 = ex2(acc[mi][ni][2]);
                    float e3 = ex2(acc[mi][ni][3]);
                    __stcs(reinterpret_cast<float2*>(r0p + ni * 8), make_float2(e0 * inv0, e1 * inv0));
                    __stcs(reinterpret_cast<float2*>(r8p + ni * 8), make_float2(e2 * inv8, e3 * inv8));
                }
            }
        } else {
#pragma unroll
            for (int mi = 0; mi < 2; ++mi) {
                const int rg = m0 + wm * 32 + mi * 16 + g;
                float s0 = 0.0f, s8 = 0.0f;
#pragma unroll
                for (int ni = 0; ni < 8; ++ni) {
                    s0 += ex2(acc[mi][ni][0]) + ex2(acc[mi][ni][1]);
                    s8 += ex2(acc[mi][ni][2]) + ex2(acc[mi][ni][3]);
                }
                s0 += __shfl_xor_sync(0xffffffffu, s0, 1);
                s0 += __shfl_xor_sync(0xffffffffu, s0, 2);
                s8 += __shfl_xor_sync(0xffffffffu, s8, 1);
                s8 += __shfl_xor_sync(0xffffffffu, s8, 2);
                if (t == 0) {
                    int pcol = blk * 2 + wn;
                    g_partials[(size_t)rg * NBLK2 + pcol]       = s0;
                    g_partials[(size_t)(rg + 8) * NBLK2 + pcol] = s8;
                }
            }
            // completion accounting; last finisher computes strip rowinv
            __syncthreads();
            if (tid == 0) {
                __threadfence();
                uint32_t old = atomicAdd(&g_done1[strip], 1u);
                sh_last = (old == NBLK - 1) ? 1u : 0u;
            }
            __syncthreads();
            if (sh_last) {
                if (tid == 0) __threadfence();
                __syncthreads();
                // 8 warps x 16 rows
                for (int rr = 0; rr < 16; ++rr) {
                    int row = m0 + wid * 16 + rr;
                    float s = 0.0f;
                    for (int i = lane; i < NBLK2; i += 32)
                        s += __ldcg(&g_partials[(size_t)row * NBLK2 + i]);
#pragma unroll
                    for (int off = 16; off >= 1; off >>= 1)
                        s += __shfl_xor_sync(0xffffffffu, s, off);
                    if (lane == 0) g_rowinv[row] = 1.0f / s;
                }
                __syncthreads();
                if (tid == 0) {
                    __threadfence();
                    atomicExch(&g_flag2[strip], 1u);
                }
            }
        }
    }
}

// ---------------------------------------------------------------------------
__global__ void tail_kernel(float* __restrict__ out, long long base, long long n) {
    long long i = (long long)blockIdx.x * 256 + threadIdx.x;
    if (i < n) out[base + i] = 0.0f;
}

extern "C" void kernel_launch(void* const* d_in, const int* in_sizes, int n_in,
                              void* d_out, int out_size) {
    const float* x = (const float*)d_in[0];
    const float* w = (const float*)d_in[1];
    float* out = (float*)d_out;

    const int smem_bytes = 2 * 128 * PITCH * 4;   // 36864
    static int attr_set = 0;
    if (!attr_set) {
        cudaFuncSetAttribute(fused_kernel,
                             cudaFuncAttributeMaxDynamicSharedMemorySize, smem_bytes);
        attr_set = 1;
    }

    init_kernel<<<1, 64>>>();
    prep_w_kernel<<<D_OUT / 256, 256>>>(w);
    prep_x_kernel<<<NROWS * 2 / 256, 256>>>(x);

    fused_kernel<<<296, 256, smem_bytes>>>(out);

    long long n_main = (long long)NROWS * D_OUT;
    long long tail = (long long)out_size - n_main;
    if (tail > 0) {
        int blocks = (int)((tail + 255) / 256);
        tail_kernel<<<blocks, 256>>>(out, n_main, tail);
    }
}

// round 11
// speedup vs baseline: 1.3797x; 1.3797x over previous
#include <cuda_runtime.h>
#include <cuda_fp16.h>
#include <cstdint>

#define NROWS 8192
#define D_IN  64
#define D_OUT 32000
#define MT 128
#define NT 128
#define NBLK   (D_OUT / NT)     // 250
#define NBLK2  (NBLK * 2)       // 500 partials per row
#define NSTRIP (NROWS / MT)     // 64 row strips
#define LAG    2                // pass2 trails pass1 by 2 groups (1000 tickets)
#define NGROUP (NSTRIP + LAG)   // 66 ticket groups
#define NTICK  (NGROUP * 500)   // 33000 tickets

// smem rows: 32 words fp16 + 4 pad = 36 words (144B) -> all ldmatrix phases
// bank-conflict-free.
#define PITCH 36
#define LOG2E 1.4426950408889634f

// -------------------- device scratch --------------------
__device__ uint32_t g_wprep[D_OUT * 32];   // [n][32] f16x2 of W^T * log2e
__device__ uint32_t g_xprep[NROWS * 32];   // [row][32] f16x2 of 1/x
__device__ float    g_partials[NROWS * NBLK2];
__device__ float    g_rowinv[NROWS];
__device__ uint32_t g_ticket;
__device__ uint32_t g_done1[NSTRIP];
__device__ uint32_t g_flag2[NSTRIP];

__device__ __forceinline__ uint32_t pack_h2(float a, float b) {
    uint32_t lo = __half_as_ushort(__float2half_rn(a));
    uint32_t hi = __half_as_ushort(__float2half_rn(b));
    return lo | (hi << 16);
}
__device__ __forceinline__ uint32_t smem_u32(const void* p) {
    uint32_t a;
    asm("{ .reg .u64 t; cvta.to.shared.u64 t, %1; cvt.u32.u64 %0, t; }" : "=r"(a) : "l"(p));
    return a;
}
__device__ __forceinline__ void cpa16(uint32_t s, const void* g) {
    asm volatile("cp.async.cg.shared.global [%0], [%1], 16;" :: "r"(s), "l"(g));
}
__device__ __forceinline__ void ldsm4(uint32_t* r, uint32_t a) {
    asm volatile("ldmatrix.sync.aligned.m8n8.x4.shared.b16 {%0,%1,%2,%3}, [%4];"
                 : "=r"(r[0]), "=r"(r[1]), "=r"(r[2]), "=r"(r[3]) : "r"(a));
}
__device__ __forceinline__ void mma_f16(float* c, const uint32_t* a, uint32_t b0, uint32_t b1) {
    asm volatile(
        "mma.sync.aligned.m16n8k16.row.col.f32.f16.f16.f32 "
        "{%0,%1,%2,%3}, {%4,%5,%6,%7}, {%8,%9}, {%0,%1,%2,%3};"
        : "+f"(c[0]), "+f"(c[1]), "+f"(c[2]), "+f"(c[3])
        : "r"(a[0]), "r"(a[1]), "r"(a[2]), "r"(a[3]), "r"(b0), "r"(b1));
}
__device__ __forceinline__ float ex2(float x) {
    float y;
    asm("ex2.approx.f32 %0, %1;" : "=f"(y) : "f"(x));
    return y;
}

// ---------------------------------------------------------------------------
__global__ void init_kernel() {
    int i = threadIdx.x;
    if (i == 0) g_ticket = 0;
    if (i < NSTRIP) { g_done1[i] = 0; g_flag2[i] = 0; }
}

// ---------------------------------------------------------------------------
// prep_w: W[64][32000] * log2e -> fp16 rows [n][32 words]
// ---------------------------------------------------------------------------
__global__ __launch_bounds__(256) void prep_w_kernel(const float* __restrict__ w) {
    int n = blockIdx.x * 256 + threadIdx.x;
    uint32_t hi[32];
#pragma unroll
    for (int j = 0; j < 32; ++j) {
        float v0 = w[(2 * j) * D_OUT + n] * LOG2E;
        float v1 = w[(2 * j + 1) * D_OUT + n] * LOG2E;
        hi[j] = pack_h2(v0, v1);
    }
    uint4* d = reinterpret_cast<uint4*>(g_wprep) + (size_t)n * 8;
#pragma unroll
    for (int j = 0; j < 8; ++j)
        d[j] = make_uint4(hi[4*j], hi[4*j+1], hi[4*j+2], hi[4*j+3]);
}

// ---------------------------------------------------------------------------
// prep_x: x[8192][64] -> fp16 rows [r][32 words] of 1/x. 2 threads per row.
// ---------------------------------------------------------------------------
__global__ __launch_bounds__(256) void prep_x_kernel(const float* __restrict__ x) {
    int tid = blockIdx.x * 256 + threadIdx.x;
    int row = tid >> 1, half = tid & 1;
    const float4* xr = reinterpret_cast<const float4*>(&x[(size_t)row * D_IN + half * 32]);
    uint32_t hi[16];
#pragma unroll
    for (int j = 0; j < 8; ++j) {
        float4 v = xr[j];
        hi[2*j]   = pack_h2(1.0f / v.x, 1.0f / v.y);
        hi[2*j+1] = pack_h2(1.0f / v.z, 1.0f / v.w);
    }
    uint4* d = reinterpret_cast<uint4*>(g_xprep) + (size_t)row * 8 + half * 4;
#pragma unroll
    for (int j = 0; j < 4; ++j)
        d[j] = make_uint4(hi[4*j], hi[4*j+1], hi[4*j+2], hi[4*j+3]);
}

// ---------------------------------------------------------------------------
// Persistent fused kernel: work-queue over 66 groups of 500 tickets.
// Group g: tickets [0,250)   = pass1 tiles of strip g      (if g < 64),
//          tickets [250,500) = pass2 tiles of strip g-LAG  (if g >= LAG).
// LAG=2 -> a strip's pass2 tickets sit >=1000 tickets after its pass1
// tickets; with ~296 tickets in flight the flag2 spin never engages in
// steady state.
// ---------------------------------------------------------------------------
__global__ __launch_bounds__(256, 2)
void fused_kernel(float* __restrict__ out) {
    extern __shared__ uint32_t smem[];
    uint32_t* sA = smem;                 // [128][36]
    uint32_t* sB = smem + 128 * PITCH;   // [128][36]
    __shared__ uint32_t sh_ticket;
    __shared__ uint32_t sh_last;

    const int tid  = threadIdx.x;
    const int wid  = tid >> 5;
    const int lane = tid & 31;
    const uint32_t sA_a = smem_u32(sA);
    const uint32_t sB_a = smem_u32(sB);

    // fragment lane constants
    const int wm = wid & 3;
    const int wn = wid >> 2;
    const int g  = lane >> 2;
    const int t  = lane & 3;
    const int arow = lane & 15;
    const int ako  = (lane >> 4) * 16;
    const int brow = (lane & 7) + ((lane >> 4) & 1) * 8;
    const int bko  = ((lane >> 3) & 1) * 16;

    for (;;) {
        __syncthreads();     // protect smem from previous tile's readers
        if (tid == 0) sh_ticket = atomicAdd(&g_ticket, 1u);
        __syncthreads();
        const uint32_t tk = sh_ticket;
        if (tk >= NTICK) break;

        const int grp = tk / 500;
        const int r   = tk % 500;
        const int is_p2 = (r >= 250);
        const int strip = is_p2 ? (grp - LAG) : grp;
        const int blk   = is_p2 ? (r - 250) : r;
        if ((!is_p2 && grp >= NSTRIP) || (is_p2 && grp < LAG)) continue;  // no-op

        const int m0 = strip * MT;
        const int n0 = blk * NT;

        // ---- prologue: cp.async both tiles (1024 uint4 each, 4/thread) ----
        {
            const uint4* gA = reinterpret_cast<const uint4*>(g_xprep + (size_t)m0 * 32);
            const uint4* gB = reinterpret_cast<const uint4*>(g_wprep + (size_t)n0 * 32);
#pragma unroll
            for (int j = 0; j < 4; ++j) {
                int f = tid + 256 * j;
                uint32_t doff = ((f >> 3) * PITCH + (f & 7) * 4) * 4;
                cpa16(sA_a + doff, gA + f);
                cpa16(sB_a + doff, gB + f);
            }
            asm volatile("cp.async.commit_group;" ::: "memory");
        }

        // ---- pass2: wait for this strip's rowinv (hidden behind cp.async) ----
        if (is_p2) {
            if (tid == 0) {
                while (*(volatile uint32_t*)&g_flag2[strip] == 0u) __nanosleep(128);
                __threadfence();
            }
        }

        asm volatile("cp.async.wait_group 0;" ::: "memory");
        __syncthreads();

        // ---- fragment addresses ----
        uint32_t aBase[2];
#pragma unroll
        for (int mi = 0; mi < 2; ++mi)
            aBase[mi] = sA_a + (uint32_t)(wm * 32 + mi * 16 + arow) * (PITCH * 4u) + ako;
        uint32_t bBase[4];
#pragma unroll
        for (int np = 0; np < 4; ++np)
            bBase[np] = sB_a + (uint32_t)((wn * 64 + np * 16 + brow) * (PITCH * 4u)) + bko;

        float acc[2][8][4];
#pragma unroll
        for (int mi = 0; mi < 2; ++mi)
#pragma unroll
            for (int ni = 0; ni < 8; ++ni)
#pragma unroll
                for (int c = 0; c < 4; ++c) acc[mi][ni][c] = 0.0f;

        // ---- mainloop ----
#pragma unroll
        for (int kc = 0; kc < 4; ++kc) {
            const uint32_t ko = kc * 32u;
            uint32_t ah[2][4];
#pragma unroll
            for (int mi = 0; mi < 2; ++mi)
                ldsm4(ah[mi], aBase[mi] + ko);
#pragma unroll
            for (int np = 0; np < 4; ++np) {
                uint32_t b[4];
                ldsm4(b, bBase[np] + ko);
#pragma unroll
                for (int mi = 0; mi < 2; ++mi) {
                    mma_f16(acc[mi][2*np],     ah[mi], b[0], b[1]);
                    mma_f16(acc[mi][2*np + 1], ah[mi], b[2], b[3]);
                }
            }
        }

        // ---- epilogue ----
        if (is_p2) {
#pragma unroll
            for (int mi = 0; mi < 2; ++mi) {
                const int rg = m0 + wm * 32 + mi * 16 + g;
                const float inv0 = __ldcg(&g_rowinv[rg]);
                const float inv8 = __ldcg(&g_rowinv[rg + 8]);
                float* r0p = out + (size_t)rg * D_OUT + n0 + wn * 64 + t * 2;
                float* r8p = r0p + (size_t)8 * D_OUT;
#pragma unroll
                for (int ni = 0; ni < 8; ++ni) {
                    float e0 = ex2(acc[mi][ni][0]);
                    float e1 = ex2(acc[mi][ni][1]);
                    float e2 = ex2(acc[mi][ni][2]);
                    float e3 = ex2(acc[mi][ni][3]);
                    __stcs(reinterpret_cast<float2*>(r0p + ni * 8), make_float2(e0 * inv0, e1 * inv0));
                    __stcs(reinterpret_cast<float2*>(r8p + ni * 8), make_float2(e2 * inv8, e3 * inv8));
                }
            }
        } else {
#pragma unroll
            for (int mi = 0; mi < 2; ++mi) {
                const int rg = m0 + wm * 32 + mi * 16 + g;
                float s0 = 0.0f, s8 = 0.0f;
#pragma unroll
                for (int ni = 0; ni < 8; ++ni) {
                    s0 += ex2(acc[mi][ni][0]) + ex2(acc[mi][ni][1]);
                    s8 += ex2(acc[mi][ni][2]) + ex2(acc[mi][ni][3]);
                }
                s0 += __shfl_xor_sync(0xffffffffu, s0, 1);
                s0 += __shfl_xor_sync(0xffffffffu, s0, 2);
                s8 += __shfl_xor_sync(0xffffffffu, s8, 1);
                s8 += __shfl_xor_sync(0xffffffffu, s8, 2);
                if (t == 0) {
                    int pcol = blk * 2 + wn;
                    g_partials[(size_t)rg * NBLK2 + pcol]       = s0;
                    g_partials[(size_t)(rg + 8) * NBLK2 + pcol] = s8;
                }
            }
            // completion accounting; last finisher computes strip rowinv
            __syncthreads();
            if (tid == 0) {
                __threadfence();
                uint32_t old = atomicAdd(&g_done1[strip], 1u);
                sh_last = (old == NBLK - 1) ? 1u : 0u;
            }
            __syncthreads();
            if (sh_last) {
                // 8 warps x 16 rows
                for (int rr = 0; rr < 16; ++rr) {
                    int row = m0 + wid * 16 + rr;
                    float s = 0.0f;
                    for (int i = lane; i < NBLK2; i += 32)
                        s += __ldcg(&g_partials[(size_t)row * NBLK2 + i]);
#pragma unroll
                    for (int off = 16; off >= 1; off >>= 1)
                        s += __shfl_xor_sync(0xffffffffu, s, off);
                    if (lane == 0) g_rowinv[row] = 1.0f / s;
                }
                __syncthreads();
                if (tid == 0) {
                    __threadfence();
                    atomicExch(&g_flag2[strip], 1u);
                }
            }
        }
    }
}

// ---------------------------------------------------------------------------
__global__ void tail_kernel(float* __restrict__ out, long long base, long long n) {
    long long i = (long long)blockIdx.x * 256 + threadIdx.x;
    if (i < n) out[base + i] = 0.0f;
}

extern "C" void kernel_launch(void* const* d_in, const int* in_sizes, int n_in,
                              void* d_out, int out_size) {
    const float* x = (const float*)d_in[0];
    const float* w = (const float*)d_in[1];
    float* out = (float*)d_out;

    const int smem_bytes = 2 * 128 * PITCH * 4;   // 36864
    static int attr_set = 0;
    if (!attr_set) {
        cudaFuncSetAttribute(fused_kernel,
                             cudaFuncAttributeMaxDynamicSharedMemorySize, smem_bytes);
        attr_set = 1;
    }

    init_kernel<<<1, 64>>>();
    prep_w_kernel<<<D_OUT / 256, 256>>>(w);
    prep_x_kernel<<<NROWS * 2 / 256, 256>>>(x);

    fused_kernel<<<296, 256, smem_bytes>>>(out);

    long long n_main = (long long)NROWS * D_OUT;
    long long tail = (long long)out_size - n_main;
    if (tail > 0) {
        int blocks = (int)((tail + 255) / 256);
        tail_kernel<<<blocks, 256>>>(out, n_main, tail);
    }
}